// round 1
// baseline (speedup 1.0000x reference)
#include <cuda_runtime.h>

#define T_HOR 100
#define B_BATCH 512
#define REGU 1e-6f

// gain scratch: K (8x24) and kv (8) per (b,t).  41 MB, fits in L2.
__device__ float g_K[B_BATCH * T_HOR * 8 * 24];
__device__ float g_kv[B_BATCH * T_HOR * 8];

// shared strides:
//  sAB : 24 x 36   (A|B row-major, rows j, cols c<32; 36 keeps float4 alignment)
//  sABt: 32 x 25   (transpose: [c][j])
//  sV  : 24 x 25
//  sC  : 32 x 36
//  sG  : 24 x 36   (G = V*[A|B]; reused as W = Vn before symmetrization)
//  sH  : 32 x 36   (H = C + [A|B]^T V [A|B]  -> Qxx/Qux/Quu blocks)
//  sK  : 8 x 28
//  sQi : 8 x 9     (Quu^{-1})

extern "C" __global__ void __launch_bounds__(256, 4)
lqr_kernel(const float* __restrict__ d_x0,
           const float* __restrict__ d_C,
           const float* __restrict__ d_c,
           const float* __restrict__ d_Cf,
           const float* __restrict__ d_cf,
           const float* __restrict__ d_xref,
           const float* __restrict__ d_uref,
           const float* __restrict__ d_A,
           const float* __restrict__ d_B,
           float* __restrict__ d_out)
{
    __shared__ float sAB[24 * 36];
    __shared__ float sABt[32 * 25];
    __shared__ float sV[24 * 25];
    __shared__ float sC[32 * 36];
    __shared__ float sG[24 * 36];
    __shared__ float sH[32 * 36];
    __shared__ float sK[8 * 28];
    __shared__ float sQi[8 * 9];
    __shared__ float sq[32], sQ[32], sc2[32], szref[32], sv[32], skv[8], su[8];
    __shared__ float sx[2][24];

    const int tid = threadIdx.x;
    const int b = blockIdx.x;

    // ---------------- preamble ----------------
    // load [A|B] and its transpose (constant across batch/time)
    for (int e = tid; e < 24 * 32; e += 256) {
        int j = e >> 5, cc = e & 31;
        float val = (cc < 24) ? d_A[j * 24 + cc] : d_B[j * 8 + (cc - 24)];
        sAB[j * 36 + cc] = val;
        sABt[cc * 25 + j] = val;
    }
    // V_T = C_final[:24,:24]
    for (int e = tid; e < 576; e += 256) {
        int i = e / 24, j = e - i * 24;
        sV[i * 25 + j] = d_Cf[(size_t)b * 1024 + i * 32 + j];
    }
    // x_ref[:, T] into sQ scratch
    if (tid < 24) sQ[tid] = d_xref[((size_t)b * 101 + 100) * 24 + tid];
    // load C[b][T-1], c, zref(T-1)
    {
        const float4 v4 = ((const float4*)(d_C + ((size_t)b * T_HOR + 99) * 1024))[tid];
        *(float4*)(sC + (tid >> 3) * 36 + ((tid & 7) << 2)) = v4;
        if (tid < 32)
            sc2[tid] = d_c[((size_t)b * T_HOR + 99) * 32 + tid];
        else if (tid < 56)
            szref[tid - 32] = d_xref[((size_t)b * 101 + 99) * 24 + (tid - 32)];
        else if (tid < 64)
            szref[24 + tid - 56] = d_uref[((size_t)b * T_HOR + 99) * 8 + (tid - 56)];
    }
    __syncthreads();
    // v_T = c_final[:24] - V_T @ x_ref[:,T]
    if (tid < 24) {
        float acc = d_cf[b * 32 + tid];
        #pragma unroll
        for (int j = 0; j < 24; j++) acc -= sV[tid * 25 + j] * sQ[j];
        sv[tid] = acc;
    }
    __syncthreads();

    // ---------------- backward Riccati ----------------
    for (int t = 99; t >= 0; --t) {
        // prefetch tile for t-1 into registers
        float4 pc4 = make_float4(0.f, 0.f, 0.f, 0.f);
        float psc = 0.f;
        if (t > 0) {
            pc4 = ((const float4*)(d_C + ((size_t)b * T_HOR + t - 1) * 1024))[tid];
            if (tid < 32)
                psc = d_c[((size_t)b * T_HOR + t - 1) * 32 + tid];
            else if (tid < 56)
                psc = d_xref[((size_t)b * 101 + t - 1) * 24 + (tid - 32)];
            else if (tid < 64)
                psc = d_uref[((size_t)b * T_HOR + t - 1) * 8 + (tid - 56)];
        }

        // stage A: G = V * [A|B]   (768 outs)  and  q = c - C*zref (32 outs)
        if (tid < 192) {
            const int i = tid >> 3, c4 = (tid & 7) << 2;
            float a0 = 0.f, a1 = 0.f, a2 = 0.f, a3 = 0.f;
            #pragma unroll
            for (int j = 0; j < 24; j++) {
                const float vij = sV[i * 25 + j];
                const float4 ab = *(const float4*)(sAB + j * 36 + c4);
                a0 += vij * ab.x; a1 += vij * ab.y; a2 += vij * ab.z; a3 += vij * ab.w;
            }
            *(float4*)(sG + i * 36 + c4) = make_float4(a0, a1, a2, a3);
        } else if (tid < 224) {
            const int r = tid - 192;
            float acc = sc2[r];
            #pragma unroll
            for (int j = 0; j < 32; j++) acc -= sC[r * 36 + j] * szref[j];
            sq[r] = acc;
        }
        __syncthreads();

        // stage B: H = C + [A|B]^T G  (+ REG on Quu diagonal)   (1024 outs)
        {
            const int r = tid >> 3, s4 = (tid & 7) << 2;
            float4 acc = *(const float4*)(sC + r * 36 + s4);
            #pragma unroll
            for (int j = 0; j < 24; j++) {
                const float ajr = sABt[r * 25 + j];
                const float4 g = *(const float4*)(sG + j * 36 + s4);
                acc.x += ajr * g.x; acc.y += ajr * g.y;
                acc.z += ajr * g.z; acc.w += ajr * g.w;
            }
            if (r >= 24) {
                const int d = r - s4;
                if (d >= 0 && d < 4) (&acc.x)[d] += REGU;
            }
            *(float4*)(sH + r * 36 + s4) = acc;
        }
        __syncthreads();

        // stage C (overlapped): commit prefetch; Qx/Qu; warp0 does 8x8 Gauss-Jordan
        if (t > 0) {
            *(float4*)(sC + (tid >> 3) * 36 + ((tid & 7) << 2)) = pc4;
            if (tid < 32) sc2[tid] = psc;
            else if (tid < 64) szref[tid - 32] = psc;
        }
        if (tid >= 64 && tid < 96) {
            const int r2 = tid - 64;
            float acc = sq[r2];
            #pragma unroll
            for (int j = 0; j < 24; j++) acc += sv[j] * sABt[r2 * 25 + j];
            sQ[r2] = acc;
        }
        if (tid < 32) {
            const int r8 = tid & 7;
            float m[16];
            #pragma unroll
            for (int j = 0; j < 8; j++) m[j] = sH[(24 + r8) * 36 + 24 + j];
            #pragma unroll
            for (int j = 0; j < 8; j++) m[8 + j] = (j == r8) ? 1.0f : 0.0f;
            #pragma unroll
            for (int cc = 0; cc < 8; cc++) {
                const float piv = __shfl_sync(0xffffffffu, m[cc], cc);
                const float inv = __fdividef(1.0f, piv);
                const float f = m[cc] * inv;
                #pragma unroll
                for (int j = 0; j < 16; j++) {
                    const float prj = __shfl_sync(0xffffffffu, m[j], cc);
                    m[j] = (r8 == cc) ? (prj * inv) : (m[j] - f * prj);
                }
            }
            if (tid < 8) {
                #pragma unroll
                for (int j = 0; j < 8; j++) sQi[r8 * 9 + j] = m[8 + j];
            }
        }
        __syncthreads();

        // stage D: K = -Quu^{-1} Qux ; kv = -Quu^{-1} Qu
        if (tid < 48) {
            const int a = tid / 6, k4 = (tid % 6) << 2;
            float a0 = 0.f, a1 = 0.f, a2 = 0.f, a3 = 0.f;
            #pragma unroll
            for (int bq = 0; bq < 8; bq++) {
                const float qab = sQi[a * 9 + bq];
                const float4 qx = *(const float4*)(sH + (24 + bq) * 36 + k4);
                a0 -= qab * qx.x; a1 -= qab * qx.y; a2 -= qab * qx.z; a3 -= qab * qx.w;
            }
            const float4 kv4 = make_float4(a0, a1, a2, a3);
            *(float4*)(sK + a * 28 + k4) = kv4;
            *(float4*)(g_K + ((size_t)(b * T_HOR + t) * 8 + a) * 24 + k4) = kv4;
        } else if (tid < 56) {
            const int a = tid - 48;
            float acc = 0.f;
            #pragma unroll
            for (int bq = 0; bq < 8; bq++) acc -= sQi[a * 9 + bq] * sQ[24 + bq];
            skv[a] = acc;
            g_kv[(size_t)(b * T_HOR + t) * 8 + a] = acc;
        }
        __syncthreads();

        // stage E: W = Qxx + Qux^T K -> sG ; vn = Qx + Qux^T kv -> sv
        if (tid < 144) {
            const int i = tid / 6, k4 = (tid % 6) << 2;
            float4 acc = *(const float4*)(sH + i * 36 + k4);
            #pragma unroll
            for (int a = 0; a < 8; a++) {
                const float qai = sH[(24 + a) * 36 + i];
                const float4 kk = *(const float4*)(sK + a * 28 + k4);
                acc.x += qai * kk.x; acc.y += qai * kk.y;
                acc.z += qai * kk.z; acc.w += qai * kk.w;
            }
            *(float4*)(sG + i * 36 + k4) = acc;
        } else if (tid < 168) {
            const int i = tid - 144;
            float acc = sQ[i];
            #pragma unroll
            for (int a = 0; a < 8; a++) acc += sH[(24 + a) * 36 + i] * skv[a];
            sv[i] = acc;
        }
        __syncthreads();

        // stage F: symmetrize -> V
        for (int e = tid; e < 576; e += 256) {
            const int i = e / 24, k = e - i * 24;
            sV[i * 25 + k] = 0.5f * (sG[i * 36 + k] + sG[k * 36 + i]);
        }
        __syncthreads();
    }

    // ---------------- forward rollout ----------------
    float* ob = d_out + (size_t)b * 3224;
    if (tid < 24) {
        const float xi = d_x0[b * 24 + tid];
        sx[0][tid] = xi;
        ob[tid] = xi;
    }
    float kreg = 0.f;
    if (tid < 192)
        kreg = g_K[(size_t)(b * T_HOR) * 192 + tid];
    else if (tid < 200)
        kreg = g_kv[(size_t)(b * T_HOR) * 8 + (tid - 192)];
    __syncthreads();

    int cur = 0;
    for (int t = 0; t < T_HOR; t++) {
        if (tid < 192)
            sK[(tid / 24) * 28 + (tid % 24)] = kreg;
        else if (tid < 200)
            skv[tid - 192] = kreg;
        __syncthreads();
        if (t < T_HOR - 1) {
            if (tid < 192)
                kreg = g_K[(size_t)(b * T_HOR + t + 1) * 192 + tid];
            else if (tid < 200)
                kreg = g_kv[(size_t)(b * T_HOR + t + 1) * 8 + (tid - 192)];
        }
        // u = K x + kv   (warp a computes u[a] via shuffle reduce)
        {
            const int a = tid >> 5, l = tid & 31;
            float p = (l < 24) ? sK[a * 28 + l] * sx[cur][l] : 0.0f;
            p += __shfl_down_sync(0xffffffffu, p, 16);
            p += __shfl_down_sync(0xffffffffu, p, 8);
            p += __shfl_down_sync(0xffffffffu, p, 4);
            p += __shfl_down_sync(0xffffffffu, p, 2);
            p += __shfl_down_sync(0xffffffffu, p, 1);
            if (l == 0) {
                const float u = p + skv[a];
                su[a] = u;
                ob[2424 + t * 8 + a] = u;
            }
        }
        __syncthreads();
        // x' = A x + B u
        if (tid < 24) {
            float acc = 0.f;
            #pragma unroll
            for (int j = 0; j < 24; j++) acc += sAB[tid * 36 + j] * sx[cur][j];
            #pragma unroll
            for (int a = 0; a < 8; a++) acc += sAB[tid * 36 + 24 + a] * su[a];
            sx[1 - cur][tid] = acc;
            ob[(t + 1) * 24 + tid] = acc;
        }
        __syncthreads();
        cur = 1 - cur;
    }
}

extern "C" void kernel_launch(void* const* d_in, const int* in_sizes, int n_in,
                              void* d_out, int out_size)
{
    const float* x0   = (const float*)d_in[0];
    const float* C    = (const float*)d_in[1];
    const float* c    = (const float*)d_in[2];
    const float* Cf   = (const float*)d_in[3];
    const float* cf   = (const float*)d_in[4];
    const float* xref = (const float*)d_in[5];
    const float* uref = (const float*)d_in[6];
    const float* A    = (const float*)d_in[7];
    const float* B    = (const float*)d_in[8];

    lqr_kernel<<<B_BATCH, 256>>>(x0, C, c, Cf, cf, xref, uref, A, B, (float*)d_out);
}

// round 2
// speedup vs baseline: 1.2077x; 1.2077x over previous
#include <cuda_runtime.h>

#define T_HOR 100
#define B_BATCH 512
#define REGU 1e-6f

// gain scratch: K (8x24) and kv (8) per (b,t). ~41 MB, fits in L2.
__device__ float g_K[B_BATCH * T_HOR * 8 * 24];
__device__ float g_kv[B_BATCH * T_HOR * 8];

extern "C" __global__ void __launch_bounds__(256, 4)
lqr_kernel(const float* __restrict__ d_x0,
           const float* __restrict__ d_C,
           const float* __restrict__ d_c,
           const float* __restrict__ d_Cf,
           const float* __restrict__ d_cf,
           const float* __restrict__ d_xref,
           const float* __restrict__ d_uref,
           const float* __restrict__ d_A,
           const float* __restrict__ d_B,
           float* __restrict__ d_out)
{
    __shared__ __align__(16) float sAB[24 * 36];   // [A|B], rows j (24), cols c (32)
    __shared__ __align__(16) float sV[24 * 28];    // symmetric V
    __shared__ __align__(16) float sC[32 * 36];    // current C tile
    __shared__ __align__(16) float sG[24 * 36];    // G = V*[A|B]
    __shared__ __align__(16) float sH[32 * 36];    // H = C + [A|B]^T V [A|B]
    __shared__ __align__(16) float sK[8 * 28];
    __shared__ float sQi[8 * 9];
    __shared__ __align__(16) float sq[32], sQ[32], sc2[32], szref[32], sv[32];
    __shared__ float skv[8], su[8];
    __shared__ float sx[2][24];

    const int tid = threadIdx.x;
    const int b = blockIdx.x;

    // triangle-pair mapping for stage E (tid < 21): ti >= tk over 6x6 4-tiles
    int e_ti = 0, e_tk = 0;
    {
        int s = 0;
        #pragma unroll
        for (int i = 0; i < 6; i++) {
            if (tid >= s && tid < s + i + 1) { e_ti = i; e_tk = tid - s; }
            s += i + 1;
        }
    }

    // ---------------- preamble ----------------
    for (int e = tid; e < 24 * 32; e += 256) {
        int j = e >> 5, cc = e & 31;
        float val = (cc < 24) ? d_A[j * 24 + cc] : d_B[j * 8 + (cc - 24)];
        sAB[j * 36 + cc] = val;
    }
    for (int e = tid; e < 576; e += 256) {
        int i = e / 24, j = e - i * 24;
        sV[i * 28 + j] = d_Cf[(size_t)b * 1024 + i * 32 + j];   // symmetric
    }
    if (tid < 24) sQ[tid] = d_xref[((size_t)b * 101 + 100) * 24 + tid];
    {
        const float4 v4 = ((const float4*)(d_C + ((size_t)b * T_HOR + 99) * 1024))[tid];
        *(float4*)(sC + (tid >> 3) * 36 + ((tid & 7) << 2)) = v4;
        if (tid < 32)
            sc2[tid] = d_c[((size_t)b * T_HOR + 99) * 32 + tid];
        else if (tid < 56)
            szref[tid - 32] = d_xref[((size_t)b * 101 + 99) * 24 + (tid - 32)];
        else if (tid < 64)
            szref[24 + tid - 56] = d_uref[((size_t)b * T_HOR + 99) * 8 + (tid - 56)];
    }
    __syncthreads();
    if (tid < 24) {
        float acc = d_cf[b * 32 + tid];
        #pragma unroll
        for (int j = 0; j < 24; j++) acc -= sV[tid * 28 + j] * sQ[j];
        sv[tid] = acc;
    }
    __syncthreads();

    // ---------------- backward Riccati ----------------
    for (int t = 99; t >= 0; --t) {
        // prefetch t-1 tile into registers
        float4 pc4 = make_float4(0.f, 0.f, 0.f, 0.f);
        float psc = 0.f;
        if (t > 0) {
            pc4 = ((const float4*)(d_C + ((size_t)b * T_HOR + t - 1) * 1024))[tid];
            if (tid < 32)
                psc = d_c[((size_t)b * T_HOR + t - 1) * 32 + tid];
            else if (tid < 56)
                psc = d_xref[((size_t)b * 101 + t - 1) * 24 + (tid - 32)];
            else if (tid < 64)
                psc = d_uref[((size_t)b * T_HOR + t - 1) * 8 + (tid - 56)];
        }

        // ---- stage A: G = V * [A|B] (2x4 tiles, 96 thr) ; q = c - C z (thr 128..159)
        if (tid < 96) {
            const int i0 = (tid >> 3) * 2, c0 = (tid & 7) * 4;
            float a00=0.f,a01=0.f,a02=0.f,a03=0.f;
            float a10=0.f,a11=0.f,a12=0.f,a13=0.f;
            #pragma unroll
            for (int j = 0; j < 24; j++) {
                const float2 av = *(const float2*)(sV + j * 28 + i0);  // V[i0..i0+1][j] by symmetry
                const float4 bb = *(const float4*)(sAB + j * 36 + c0);
                a00 += av.x * bb.x; a01 += av.x * bb.y; a02 += av.x * bb.z; a03 += av.x * bb.w;
                a10 += av.y * bb.x; a11 += av.y * bb.y; a12 += av.y * bb.z; a13 += av.y * bb.w;
            }
            *(float4*)(sG + i0 * 36 + c0)       = make_float4(a00, a01, a02, a03);
            *(float4*)(sG + (i0 + 1) * 36 + c0) = make_float4(a10, a11, a12, a13);
        } else if (tid >= 128 && tid < 160) {
            const int r = tid - 128;
            float acc = sc2[r];
            #pragma unroll
            for (int j4 = 0; j4 < 8; j4++) {
                const float4 cr = *(const float4*)(sC + r * 36 + j4 * 4);
                const float4 zz = *(const float4*)(szref + j4 * 4);
                acc -= cr.x * zz.x + cr.y * zz.y + cr.z * zz.z + cr.w * zz.w;
            }
            sq[r] = acc;
        }
        __syncthreads();

        // ---- stage B: H = C + [A|B]^T G (+REG diag), 2x4 tiles, 128 thr
        if (tid < 128) {
            const int r0 = (tid >> 3) * 2, s0 = (tid & 7) * 4;
            float4 acc0 = *(const float4*)(sC + r0 * 36 + s0);
            float4 acc1 = *(const float4*)(sC + (r0 + 1) * 36 + s0);
            #pragma unroll
            for (int j = 0; j < 24; j++) {
                const float2 aa = *(const float2*)(sAB + j * 36 + r0);  // AB[j][r0..r0+1]
                const float4 gg = *(const float4*)(sG + j * 36 + s0);
                acc0.x += aa.x * gg.x; acc0.y += aa.x * gg.y; acc0.z += aa.x * gg.z; acc0.w += aa.x * gg.w;
                acc1.x += aa.y * gg.x; acc1.y += aa.y * gg.y; acc1.z += aa.y * gg.z; acc1.w += aa.y * gg.w;
            }
            {
                int e0 = r0;
                if (e0 >= 24 && e0 >= s0 && e0 < s0 + 4) (&acc0.x)[e0 - s0] += REGU;
                int e1 = r0 + 1;
                if (e1 >= 24 && e1 >= s0 && e1 < s0 + 4) (&acc1.x)[e1 - s0] += REGU;
            }
            *(float4*)(sH + r0 * 36 + s0)       = acc0;
            *(float4*)(sH + (r0 + 1) * 36 + s0) = acc1;
        }
        __syncthreads();

        // ---- stage C: commit prefetch; Qx/Qu; warp0 Gauss-Jordan of Quu
        if (t > 0) {
            *(float4*)(sC + (tid >> 3) * 36 + ((tid & 7) << 2)) = pc4;
            if (tid < 32) sc2[tid] = psc;
            else if (tid < 64) szref[tid - 32] = psc;
        }
        if (tid >= 64 && tid < 96) {
            const int r2 = tid - 64;
            float acc = sq[r2];
            #pragma unroll
            for (int j = 0; j < 24; j++) acc += sv[j] * sAB[j * 36 + r2];
            sQ[r2] = acc;
        }
        if (tid < 32) {
            const int r8 = tid & 7;
            float m[16];
            #pragma unroll
            for (int j = 0; j < 8; j++) m[j] = sH[(24 + r8) * 36 + 24 + j];
            #pragma unroll
            for (int j = 0; j < 8; j++) m[8 + j] = (j == r8) ? 1.0f : 0.0f;
            #pragma unroll
            for (int cc = 0; cc < 8; cc++) {
                const float piv = __shfl_sync(0xffffffffu, m[cc], cc);
                const float inv = __fdividef(1.0f, piv);
                const float f = m[cc] * inv;
                #pragma unroll
                for (int j = 0; j < 16; j++) {
                    const float prj = __shfl_sync(0xffffffffu, m[j], cc);
                    m[j] = (r8 == cc) ? (prj * inv) : (m[j] - f * prj);
                }
            }
            if (tid < 8) {
                #pragma unroll
                for (int j = 0; j < 8; j++) sQi[r8 * 9 + j] = m[8 + j];
            }
        }
        __syncthreads();

        // ---- stage D: K = -Quu^{-1} Qux ; kv = -Quu^{-1} Qu
        if (tid < 48) {
            const int a = tid / 6, k4 = (tid % 6) << 2;
            float a0 = 0.f, a1 = 0.f, a2 = 0.f, a3 = 0.f;
            #pragma unroll
            for (int bq = 0; bq < 8; bq++) {
                const float qab = sQi[a * 9 + bq];
                const float4 qx = *(const float4*)(sH + (24 + bq) * 36 + k4);
                a0 -= qab * qx.x; a1 -= qab * qx.y; a2 -= qab * qx.z; a3 -= qab * qx.w;
            }
            const float4 kv4 = make_float4(a0, a1, a2, a3);
            *(float4*)(sK + a * 28 + k4) = kv4;
            *(float4*)(g_K + ((size_t)(b * T_HOR + t) * 8 + a) * 24 + k4) = kv4;
        } else if (tid < 56) {
            const int a = tid - 48;
            float acc = 0.f;
            #pragma unroll
            for (int bq = 0; bq < 8; bq++) acc -= sQi[a * 9 + bq] * sQ[24 + bq];
            skv[a] = acc;
            g_kv[(size_t)(b * T_HOR + t) * 8 + a] = acc;
        }
        __syncthreads();

        // ---- stage E (fused symmetrize): V = 0.5*(W + W^T),  W = Qxx + Qux^T K
        // S[r][c] = sum_a ( Qux[a][i0+r]*K[a][k0+c] + K[a][i0+r]*Qux[a][k0+c] )
        // V(i,k)[r][c] = 0.5*( H[i0+r][k0+c] + H[k0+c][i0+r] + S[r][c] )
        if (tid < 21) {
            const int i0 = 4 * e_ti, k0 = 4 * e_tk;
            float S[4][4];
            #pragma unroll
            for (int r = 0; r < 4; r++)
                #pragma unroll
                for (int c = 0; c < 4; c++) S[r][c] = 0.f;
            #pragma unroll
            for (int a = 0; a < 8; a++) {
                const float4 fHi = *(const float4*)(sH + (24 + a) * 36 + i0);
                const float4 fHk = *(const float4*)(sH + (24 + a) * 36 + k0);
                const float4 fKi = *(const float4*)(sK + a * 28 + i0);
                const float4 fKk = *(const float4*)(sK + a * 28 + k0);
                #pragma unroll
                for (int r = 0; r < 4; r++) {
                    const float hi = (&fHi.x)[r], ki = (&fKi.x)[r];
                    #pragma unroll
                    for (int c = 0; c < 4; c++)
                        S[r][c] += hi * (&fKk.x)[c] + ki * (&fHk.x)[c];
                }
            }
            #pragma unroll
            for (int r = 0; r < 4; r++) {
                float4 vik, vki;
                #pragma unroll
                for (int c = 0; c < 4; c++) {
                    (&vik.x)[c] = 0.5f * (sH[(i0 + r) * 36 + k0 + c] + sH[(k0 + c) * 36 + i0 + r] + S[r][c]);
                    (&vki.x)[c] = 0.5f * (sH[(k0 + r) * 36 + i0 + c] + sH[(i0 + c) * 36 + k0 + r] + S[c][r]);
                }
                *(float4*)(sV + (i0 + r) * 28 + k0) = vik;
                *(float4*)(sV + (k0 + r) * 28 + i0) = vki;
            }
        } else if (tid >= 32 && tid < 56) {
            const int i = tid - 32;
            float acc = sQ[i];
            #pragma unroll
            for (int a = 0; a < 8; a++) acc += sH[(24 + a) * 36 + i] * skv[a];
            sv[i] = acc;
        }
        __syncthreads();
    }

    // ---------------- forward rollout ----------------
    float* ob = d_out + (size_t)b * 3224;
    if (tid < 24) {
        const float xi = d_x0[b * 24 + tid];
        sx[0][tid] = xi;
        ob[tid] = xi;
    }
    float kreg = 0.f;
    if (tid < 192)
        kreg = g_K[(size_t)(b * T_HOR) * 192 + tid];
    else if (tid < 200)
        kreg = g_kv[(size_t)(b * T_HOR) * 8 + (tid - 192)];
    __syncthreads();

    int cur = 0;
    for (int t = 0; t < T_HOR; t++) {
        if (tid < 192)
            sK[(tid / 24) * 28 + (tid % 24)] = kreg;
        else if (tid < 200)
            skv[tid - 192] = kreg;
        __syncthreads();
        if (t < T_HOR - 1) {
            if (tid < 192)
                kreg = g_K[(size_t)(b * T_HOR + t + 1) * 192 + tid];
            else if (tid < 200)
                kreg = g_kv[(size_t)(b * T_HOR + t + 1) * 8 + (tid - 192)];
        }
        {
            const int a = tid >> 5, l = tid & 31;
            float p = (l < 24) ? sK[a * 28 + l] * sx[cur][l] : 0.0f;
            p += __shfl_down_sync(0xffffffffu, p, 16);
            p += __shfl_down_sync(0xffffffffu, p, 8);
            p += __shfl_down_sync(0xffffffffu, p, 4);
            p += __shfl_down_sync(0xffffffffu, p, 2);
            p += __shfl_down_sync(0xffffffffu, p, 1);
            if (l == 0) {
                const float u = p + skv[a];
                su[a] = u;
                ob[2424 + t * 8 + a] = u;
            }
        }
        __syncthreads();
        if (tid < 24) {
            float acc = 0.f;
            #pragma unroll
            for (int j = 0; j < 24; j++) acc += sAB[tid * 36 + j] * sx[cur][j];
            #pragma unroll
            for (int a = 0; a < 8; a++) acc += sAB[tid * 36 + 24 + a] * su[a];
            sx[1 - cur][tid] = acc;
            ob[(t + 1) * 24 + tid] = acc;
        }
        __syncthreads();
        cur = 1 - cur;
    }
}

extern "C" void kernel_launch(void* const* d_in, const int* in_sizes, int n_in,
                              void* d_out, int out_size)
{
    const float* x0   = (const float*)d_in[0];
    const float* C    = (const float*)d_in[1];
    const float* c    = (const float*)d_in[2];
    const float* Cf   = (const float*)d_in[3];
    const float* cf   = (const float*)d_in[4];
    const float* xref = (const float*)d_in[5];
    const float* uref = (const float*)d_in[6];
    const float* A    = (const float*)d_in[7];
    const float* B    = (const float*)d_in[8];

    lqr_kernel<<<B_BATCH, 256>>>(x0, C, c, Cf, cf, xref, uref, A, B, (float*)d_out);
}

// round 3
// speedup vs baseline: 1.4591x; 1.2081x over previous
#include <cuda_runtime.h>

#define T_HOR 100
#define B_BATCH 512
#define REGU 1e-6f

// gain scratch: K (8x24) and kv (8) per (b,t). ~41 MB, L2-resident at readback.
__device__ float g_K[B_BATCH * T_HOR * 8 * 24];
__device__ float g_kv[B_BATCH * T_HOR * 8];

extern "C" __global__ void __launch_bounds__(128, 5)
lqr_kernel(const float* __restrict__ d_x0,
           const float* __restrict__ d_C,
           const float* __restrict__ d_c,
           const float* __restrict__ d_Cf,
           const float* __restrict__ d_cf,
           const float* __restrict__ d_xref,
           const float* __restrict__ d_uref,
           const float* __restrict__ d_A,
           const float* __restrict__ d_B,
           float* __restrict__ d_out)
{
    __shared__ __align__(16) float sAB[24 * 36];   // [A|B]: rows j(24), cols 0..31
    __shared__ __align__(16) float sV[24 * 28];    // symmetric V (full storage)
    __shared__ __align__(16) float sC[32 * 36];    // current C tile (full)
    __shared__ __align__(16) float sG[24 * 36];    // G = V*[A|B]
    __shared__ __align__(16) float sH[32 * 36];    // H lower triangle (+ full diag 4x4 tiles)
    __shared__ __align__(16) float sK[8 * 28];
    __shared__ __align__(16) float sK2[192];       // flat K for rollout
    __shared__ float sQi[8 * 9];
    __shared__ __align__(16) float sq[32], sQ[32], sc2[32], szref[32], sv[32];
    __shared__ float skv[8], su[8];
    __shared__ float sx[2][24];

    const int tid = threadIdx.x;
    const int b = blockIdx.x;

    // triangle tile maps
    int e_ti = 0, e_tk = 0;          // 6x6 lower triangle (21 tiles) for V
    {
        int s = 0;
        #pragma unroll
        for (int i = 0; i < 6; i++) {
            if (tid >= s && tid < s + i + 1) { e_ti = i; e_tk = tid - s; }
            s += i + 1;
        }
    }
    int b_bi = 0, b_bk = 0;          // 8x8 lower triangle (36 tiles) for H
    {
        const int tt = tid >> 1;
        int s = 0;
        #pragma unroll
        for (int i = 0; i < 8; i++) {
            if (tt >= s && tt < s + i + 1) { b_bi = i; b_bk = tt - s; }
            s += i + 1;
        }
    }

    // ---------------- preamble ----------------
    for (int e = tid; e < 24 * 32; e += 128) {
        int j = e >> 5, cc = e & 31;
        sAB[j * 36 + cc] = (cc < 24) ? d_A[j * 24 + cc] : d_B[j * 8 + (cc - 24)];
    }
    for (int e = tid; e < 576; e += 128) {
        int i = e / 24, j = e - i * 24;
        sV[i * 28 + j] = d_Cf[(size_t)b * 1024 + i * 32 + j];
    }
    if (tid < 24) sQ[tid] = d_xref[((size_t)b * 101 + 100) * 24 + tid];
    {
        const float4* C4 = (const float4*)(d_C + ((size_t)b * T_HOR + 99) * 1024);
        #pragma unroll
        for (int ss = 0; ss < 2; ss++) {
            const int s = tid + ss * 128;
            *(float4*)(sC + (s >> 3) * 36 + ((s & 7) << 2)) = C4[s];
        }
        if (tid < 32)
            sc2[tid] = d_c[((size_t)b * T_HOR + 99) * 32 + tid];
        else if (tid < 56)
            szref[tid - 32] = d_xref[((size_t)b * 101 + 99) * 24 + (tid - 32)];
        else if (tid < 64)
            szref[24 + tid - 56] = d_uref[((size_t)b * T_HOR + 99) * 8 + (tid - 56)];
    }
    __syncthreads();
    if (tid < 24) {
        float acc = d_cf[b * 32 + tid];
        #pragma unroll
        for (int j = 0; j < 24; j++) acc -= sV[tid * 28 + j] * sQ[j];
        sv[tid] = acc;
    }
    __syncthreads();

    // ---------------- backward Riccati ----------------
    for (int t = 99; t >= 0; --t) {
        // prefetch t-1 into registers (committed at stage E)
        float4 pc4a = make_float4(0.f,0.f,0.f,0.f), pc4b = pc4a;
        float psc = 0.f;
        if (t > 0) {
            const float4* C4 = (const float4*)(d_C + ((size_t)b * T_HOR + t - 1) * 1024);
            pc4a = C4[tid];
            pc4b = C4[tid + 128];
            if (tid < 32)
                psc = d_c[((size_t)b * T_HOR + t - 1) * 32 + tid];
            else if (tid < 56)
                psc = d_xref[((size_t)b * 101 + t - 1) * 24 + (tid - 32)];
            else if (tid < 64)
                psc = d_uref[((size_t)b * T_HOR + t - 1) * 8 + (tid - 56)];
        }

        // ---- stage A: G = V*[A|B] (48 thr, 4x4 tiles) ; q = c - C z (thr 64..95)
        if (tid < 48) {
            const int i0 = (tid >> 3) * 4, c0 = (tid & 7) * 4;
            float acc[4][4];
            #pragma unroll
            for (int r = 0; r < 4; r++)
                #pragma unroll
                for (int c = 0; c < 4; c++) acc[r][c] = 0.f;
            #pragma unroll
            for (int j = 0; j < 24; j++) {
                const float4 vv = *(const float4*)(sV + j * 28 + i0);  // V[i0..i0+3][j] (sym)
                const float4 bb = *(const float4*)(sAB + j * 36 + c0);
                #pragma unroll
                for (int r = 0; r < 4; r++) {
                    const float vr = (&vv.x)[r];
                    acc[r][0] += vr * bb.x; acc[r][1] += vr * bb.y;
                    acc[r][2] += vr * bb.z; acc[r][3] += vr * bb.w;
                }
            }
            #pragma unroll
            for (int r = 0; r < 4; r++)
                *(float4*)(sG + (i0 + r) * 36 + c0) =
                    make_float4(acc[r][0], acc[r][1], acc[r][2], acc[r][3]);
        } else if (tid >= 64 && tid < 96) {
            const int r = tid - 64;
            float acc = sc2[r];
            #pragma unroll
            for (int j4 = 0; j4 < 8; j4++) {
                const float4 cr = *(const float4*)(sC + r * 36 + j4 * 4);
                const float4 zz = *(const float4*)(szref + j4 * 4);
                acc -= cr.x * zz.x + cr.y * zz.y + cr.z * zz.z + cr.w * zz.w;
            }
            sq[r] = acc;
        }
        __syncthreads();

        // ---- stage B: H triangle = C + [A|B]^T G (+REG diag) (72 thr, 2x4) ; Qx/Qu (96..127)
        if (tid < 72) {
            const int r0 = b_bi * 4 + (tid & 1) * 2;   // two rows
            const int k0 = b_bk * 4;                    // four cols
            float4 acc0 = *(const float4*)(sC + r0 * 36 + k0);
            float4 acc1 = *(const float4*)(sC + (r0 + 1) * 36 + k0);
            #pragma unroll
            for (int j = 0; j < 24; j++) {
                const float2 aa = *(const float2*)(sAB + j * 36 + r0);
                const float4 gg = *(const float4*)(sG + j * 36 + k0);
                acc0.x += aa.x * gg.x; acc0.y += aa.x * gg.y; acc0.z += aa.x * gg.z; acc0.w += aa.x * gg.w;
                acc1.x += aa.y * gg.x; acc1.y += aa.y * gg.y; acc1.z += aa.y * gg.z; acc1.w += aa.y * gg.w;
            }
            if (r0 >= 24) {
                const int d0 = r0 - k0;
                if (d0 >= 0 && d0 < 4) (&acc0.x)[d0] += REGU;
                const int d1 = r0 + 1 - k0;
                if (d1 >= 0 && d1 < 4) (&acc1.x)[d1] += REGU;
            }
            *(float4*)(sH + r0 * 36 + k0)       = acc0;
            *(float4*)(sH + (r0 + 1) * 36 + k0) = acc1;
        } else if (tid >= 96) {
            const int r2 = tid - 96;
            float acc = sq[r2];
            #pragma unroll
            for (int j = 0; j < 24; j++) acc += sv[j] * sAB[j * 36 + r2];
            sQ[r2] = acc;
        }
        __syncthreads();

        // ---- stage C: warp0 Gauss-Jordan of Quu (triangle-aware reads)
        if (tid < 32) {
            const int r8 = tid & 7;
            float m[16];
            #pragma unroll
            for (int j = 0; j < 8; j++)
                m[j] = (j <= r8) ? sH[(24 + r8) * 36 + 24 + j]
                                 : sH[(24 + j) * 36 + 24 + r8];
            #pragma unroll
            for (int j = 0; j < 8; j++) m[8 + j] = (j == r8) ? 1.0f : 0.0f;
            #pragma unroll
            for (int cc = 0; cc < 8; cc++) {
                const float piv = __shfl_sync(0xffffffffu, m[cc], cc);
                const float inv = __fdividef(1.0f, piv);
                const float f = m[cc] * inv;
                #pragma unroll
                for (int j = 0; j < 16; j++) {
                    const float prj = __shfl_sync(0xffffffffu, m[j], cc);
                    m[j] = (r8 == cc) ? (prj * inv) : (m[j] - f * prj);
                }
            }
            if (tid < 8) {
                #pragma unroll
                for (int j = 0; j < 8; j++) sQi[r8 * 9 + j] = m[8 + j];
            }
        }
        __syncthreads();

        // ---- stage D: K = -Quu^{-1} Qux ; kv = -Quu^{-1} Qu
        if (tid < 48) {
            const int a = tid / 6, k4 = (tid % 6) << 2;
            float a0 = 0.f, a1 = 0.f, a2 = 0.f, a3 = 0.f;
            #pragma unroll
            for (int bq = 0; bq < 8; bq++) {
                const float qab = sQi[a * 9 + bq];
                const float4 qx = *(const float4*)(sH + (24 + bq) * 36 + k4);
                a0 -= qab * qx.x; a1 -= qab * qx.y; a2 -= qab * qx.z; a3 -= qab * qx.w;
            }
            const float4 kv4 = make_float4(a0, a1, a2, a3);
            *(float4*)(sK + a * 28 + k4) = kv4;
            *(float4*)(g_K + ((size_t)(b * T_HOR + t) * 8 + a) * 24 + k4) = kv4;
        } else if (tid < 56) {
            const int a = tid - 48;
            float acc = 0.f;
            #pragma unroll
            for (int bq = 0; bq < 8; bq++) acc -= sQi[a * 9 + bq] * sQ[24 + bq];
            skv[a] = acc;
            g_kv[(size_t)(b * T_HOR + t) * 8 + a] = acc;
        }
        __syncthreads();

        // ---- stage E: commit prefetch; V = H_tri + 0.5*S (S symmetric); vn
        if (t > 0) {
            *(float4*)(sC + (tid >> 3) * 36 + ((tid & 7) << 2)) = pc4a;
            {
                const int s = tid + 128;
                *(float4*)(sC + (s >> 3) * 36 + ((s & 7) << 2)) = pc4b;
            }
            if (tid < 32) sc2[tid] = psc;
            else if (tid < 64) szref[tid - 32] = psc;
        }
        if (tid < 21) {
            const int i0 = 4 * e_ti, k0 = 4 * e_tk;
            float S[4][4];
            #pragma unroll
            for (int r = 0; r < 4; r++)
                #pragma unroll
                for (int c = 0; c < 4; c++) S[r][c] = 0.f;
            #pragma unroll
            for (int a = 0; a < 8; a++) {
                const float4 fHi = *(const float4*)(sH + (24 + a) * 36 + i0);
                const float4 fHk = *(const float4*)(sH + (24 + a) * 36 + k0);
                const float4 fKi = *(const float4*)(sK + a * 28 + i0);
                const float4 fKk = *(const float4*)(sK + a * 28 + k0);
                #pragma unroll
                for (int r = 0; r < 4; r++) {
                    const float hi = (&fHi.x)[r], ki = (&fKi.x)[r];
                    #pragma unroll
                    for (int c = 0; c < 4; c++)
                        S[r][c] += hi * (&fKk.x)[c] + ki * (&fHk.x)[c];
                }
            }
            if (e_ti == e_tk) {
                #pragma unroll
                for (int r = 0; r < 4; r++) {
                    float4 vik;
                    #pragma unroll
                    for (int c = 0; c < 4; c++) {
                        const float hx = (c > r) ? sH[(k0 + c) * 36 + i0 + r]
                                                 : sH[(i0 + r) * 36 + k0 + c];
                        (&vik.x)[c] = hx + 0.5f * S[r][c];
                    }
                    *(float4*)(sV + (i0 + r) * 28 + k0) = vik;
                }
            } else {
                #pragma unroll
                for (int r = 0; r < 4; r++) {
                    float4 vik;
                    #pragma unroll
                    for (int c = 0; c < 4; c++) {
                        const float v = sH[(i0 + r) * 36 + k0 + c] + 0.5f * S[r][c];
                        (&vik.x)[c] = v;
                        sV[(k0 + c) * 28 + i0 + r] = v;   // mirror
                    }
                    *(float4*)(sV + (i0 + r) * 28 + k0) = vik;
                }
            }
        } else if (tid >= 32 && tid < 56) {
            const int i = tid - 32;
            float acc = sQ[i];
            #pragma unroll
            for (int a = 0; a < 8; a++) acc += sH[(24 + a) * 36 + i] * skv[a];
            sv[i] = acc;
        }
        __syncthreads();
    }

    // ---------------- forward rollout ----------------
    float* ob = d_out + (size_t)b * 3224;
    if (tid < 24) {
        const float xi = d_x0[b * 24 + tid];
        sx[0][tid] = xi;
        ob[tid] = xi;
    }
    float kr0 = 0.f, kr1 = 0.f;
    if (tid < 96) {
        const float2 k2 = *(const float2*)(g_K + (size_t)b * T_HOR * 192 + 2 * tid);
        kr0 = k2.x; kr1 = k2.y;
    } else if (tid < 104) {
        kr0 = g_kv[(size_t)b * T_HOR * 8 + (tid - 96)];
    }
    __syncthreads();

    int cur = 0;
    for (int t = 0; t < T_HOR; t++) {
        if (tid < 96)
            *(float2*)(sK2 + 2 * tid) = make_float2(kr0, kr1);
        else if (tid < 104)
            skv[tid - 96] = kr0;
        __syncthreads();
        if (t < T_HOR - 1) {
            if (tid < 96) {
                const float2 k2 = *(const float2*)(g_K + (size_t)(b * T_HOR + t + 1) * 192 + 2 * tid);
                kr0 = k2.x; kr1 = k2.y;
            } else if (tid < 104) {
                kr0 = g_kv[(size_t)(b * T_HOR + t + 1) * 8 + (tid - 96)];
            }
        }
        // u = K x + kv : 16 threads per control (8 groups)
        {
            const int a = tid >> 4, l = tid & 15;
            float p = 0.f;
            if (l < 12)
                p = sK2[a * 24 + l] * sx[cur][l] + sK2[a * 24 + l + 12] * sx[cur][l + 12];
            p += __shfl_down_sync(0xffffffffu, p, 8, 16);
            p += __shfl_down_sync(0xffffffffu, p, 4, 16);
            p += __shfl_down_sync(0xffffffffu, p, 2, 16);
            p += __shfl_down_sync(0xffffffffu, p, 1, 16);
            if (l == 0) {
                const float u = p + skv[a];
                su[a] = u;
                ob[2424 + t * 8 + a] = u;
            }
        }
        __syncthreads();
        // x' = A x + B u
        if (tid < 24) {
            float acc = 0.f;
            #pragma unroll
            for (int j = 0; j < 24; j++) acc += sAB[tid * 36 + j] * sx[cur][j];
            #pragma unroll
            for (int a = 0; a < 8; a++) acc += sAB[tid * 36 + 24 + a] * su[a];
            sx[1 - cur][tid] = acc;
            ob[(t + 1) * 24 + tid] = acc;
        }
        __syncthreads();
        cur = 1 - cur;
    }
}

extern "C" void kernel_launch(void* const* d_in, const int* in_sizes, int n_in,
                              void* d_out, int out_size)
{
    const float* x0   = (const float*)d_in[0];
    const float* C    = (const float*)d_in[1];
    const float* c    = (const float*)d_in[2];
    const float* Cf   = (const float*)d_in[3];
    const float* cf   = (const float*)d_in[4];
    const float* xref = (const float*)d_in[5];
    const float* uref = (const float*)d_in[6];
    const float* A    = (const float*)d_in[7];
    const float* B    = (const float*)d_in[8];

    lqr_kernel<<<B_BATCH, 128>>>(x0, C, c, Cf, cf, xref, uref, A, B, (float*)d_out);
}

// round 4
// speedup vs baseline: 1.8526x; 1.2697x over previous
#include <cuda_runtime.h>

#define T_HOR 100
#define B_BATCH 512
#define REGU 1e-6f

typedef unsigned long long ull;

__device__ float g_K[B_BATCH * T_HOR * 8 * 24];
__device__ float g_kv[B_BATCH * T_HOR * 8];

__device__ __forceinline__ ull pack2(float s) {
    ull d; asm("mov.b64 %0, {%1, %1};" : "=l"(d) : "f"(s)); return d;
}
__device__ __forceinline__ void ffma2(ull& d, ull a, ull b) {
    asm("fma.rn.f32x2 %0, %1, %2, %0;" : "+l"(d) : "l"(a), "l"(b));
}
__device__ __forceinline__ float2 unpack2(ull v) {
    float2 r; asm("mov.b64 {%0, %1}, %2;" : "=f"(r.x), "=f"(r.y) : "l"(v)); return r;
}

extern "C" __global__ void __launch_bounds__(128, 4)
lqr_kernel(const float* __restrict__ d_x0,
           const float* __restrict__ d_C,
           const float* __restrict__ d_c,
           const float* __restrict__ d_Cf,
           const float* __restrict__ d_cf,
           const float* __restrict__ d_xref,
           const float* __restrict__ d_uref,
           const float* __restrict__ d_A,
           const float* __restrict__ d_B,
           float* __restrict__ d_out)
{
    __shared__ __align__(16) float sAB[24 * 36];   // [A|B]: rows j(24), cols 0..31
    __shared__ __align__(16) float sV[24 * 28];    // symmetric V
    __shared__ __align__(16) float sC[32 * 36];    // current C tile
    __shared__ __align__(16) float sG[24 * 36];    // G = V*[A|B]
    __shared__ __align__(16) float sH[32 * 36];    // H lower triangle
    __shared__ __align__(16) float sK[8 * 28];
    __shared__ __align__(16) float sK2[192];       // flat K for rollout
    __shared__ __align__(16) float sQ[32], sc2[32], szref[32], sv[32];
    __shared__ float skv[8], su[8];
    __shared__ float sx[2][24];

    const int tid = threadIdx.x;
    const int b = blockIdx.x;

    // triangle tile maps (from tid>>1)
    int e_ti = 0, e_tk = 0;      // 6x6 lower tri (21 tiles) for V, 2 thr/tile
    int b_bi = 0, b_bk = 0;      // 8x8 lower tri (36 tiles) for H, 2 thr/tile
    {
        const int tt = tid >> 1;
        int s = 0;
        #pragma unroll
        for (int i = 0; i < 6; i++) {
            if (tt >= s && tt < s + i + 1) { e_ti = i; e_tk = tt - s; }
            s += i + 1;
        }
        s = 0;
        #pragma unroll
        for (int i = 0; i < 8; i++) {
            if (tt >= s && tt < s + i + 1) { b_bi = i; b_bk = tt - s; }
            s += i + 1;
        }
    }

    // ---------------- preamble ----------------
    for (int e = tid; e < 24 * 32; e += 128) {
        int j = e >> 5, cc = e & 31;
        sAB[j * 36 + cc] = (cc < 24) ? d_A[j * 24 + cc] : d_B[j * 8 + (cc - 24)];
    }
    for (int e = tid; e < 576; e += 128) {
        int i = e / 24, j = e - i * 24;
        sV[i * 28 + j] = d_Cf[(size_t)b * 1024 + i * 32 + j];
    }
    if (tid < 24) sQ[tid] = d_xref[((size_t)b * 101 + 100) * 24 + tid];
    {
        const float4* C4 = (const float4*)(d_C + ((size_t)b * T_HOR + 99) * 1024);
        #pragma unroll
        for (int ss = 0; ss < 2; ss++) {
            const int s = tid + ss * 128;
            *(float4*)(sC + (s >> 3) * 36 + ((s & 7) << 2)) = C4[s];
        }
        if (tid < 32)
            sc2[tid] = d_c[((size_t)b * T_HOR + 99) * 32 + tid];
        else if (tid < 56)
            szref[tid - 32] = d_xref[((size_t)b * 101 + 99) * 24 + (tid - 32)];
        else if (tid < 64)
            szref[24 + tid - 56] = d_uref[((size_t)b * T_HOR + 99) * 8 + (tid - 56)];
    }
    __syncthreads();
    if (tid < 24) {
        float acc = d_cf[b * 32 + tid];
        #pragma unroll
        for (int j = 0; j < 24; j++) acc -= sV[tid * 28 + j] * sQ[j];
        sv[tid] = acc;
    }
    __syncthreads();

    // ---------------- backward Riccati ----------------
    for (int t = 99; t >= 0; --t) {
        // prefetch t-1 (threads 32..127; GJ warp stays clean)
        float4 pc0 = make_float4(0.f,0.f,0.f,0.f), pc1 = pc0, pc2 = pc0;
        float psc = 0.f;
        if (t > 0 && tid >= 32) {
            const float4* C4 = (const float4*)(d_C + ((size_t)b * T_HOR + t - 1) * 1024);
            const int idx = tid - 32;
            pc0 = C4[idx];
            pc1 = C4[idx + 96];
            if (tid < 96) pc2 = C4[idx + 192];
            if (tid < 64)
                psc = d_c[((size_t)b * T_HOR + t - 1) * 32 + (tid - 32)];
            else if (tid < 88)
                psc = d_xref[((size_t)b * 101 + t - 1) * 24 + (tid - 64)];
            else if (tid < 96)
                psc = d_uref[((size_t)b * T_HOR + t - 1) * 8 + (tid - 88)];
        }

        // ---- stage A: G = V*[A|B] (96 thr, 2x4, f32x2) ; Q = [Qx|Qu] (32 thr)
        if (tid < 96) {
            const int i0 = (tid >> 3) * 2, c4 = (tid & 7) << 2;
            ull aL0 = 0, aH0 = 0, aL1 = 0, aH1 = 0;
            #pragma unroll
            for (int j = 0; j < 24; j++) {
                const float2 vv = *(const float2*)(sV + j * 28 + i0);   // V[i0..i0+1][j] (sym)
                const ulonglong2 ab = *(const ulonglong2*)(sAB + j * 36 + c4);
                const ull v0 = pack2(vv.x), v1 = pack2(vv.y);
                ffma2(aL0, v0, ab.x); ffma2(aH0, v0, ab.y);
                ffma2(aL1, v1, ab.x); ffma2(aH1, v1, ab.y);
            }
            *(ulonglong2*)(sG + i0 * 36 + c4)       = make_ulonglong2(aL0, aH0);
            *(ulonglong2*)(sG + (i0 + 1) * 36 + c4) = make_ulonglong2(aL1, aH1);
        } else {
            const int r = tid - 96;
            float acc = sc2[r];
            #pragma unroll
            for (int j4 = 0; j4 < 8; j4++) {
                const float4 cr = *(const float4*)(sC + r * 36 + j4 * 4);
                const float4 zz = *(const float4*)(szref + j4 * 4);
                acc -= cr.x * zz.x + cr.y * zz.y + cr.z * zz.z + cr.w * zz.w;
            }
            #pragma unroll
            for (int j = 0; j < 24; j++) acc += sAB[j * 36 + r] * sv[j];
            sQ[r] = acc;
        }
        __syncthreads();

        // ---- stage B: H tri = C + [A|B]^T G (+REG diag) (72 thr, 2x4, f32x2)
        if (tid < 72) {
            const int r0 = b_bi * 4 + (tid & 1) * 2;
            const int k0 = b_bk * 4;
            const ulonglong2 c0 = *(const ulonglong2*)(sC + r0 * 36 + k0);
            const ulonglong2 c1 = *(const ulonglong2*)(sC + (r0 + 1) * 36 + k0);
            ull aL0 = c0.x, aH0 = c0.y, aL1 = c1.x, aH1 = c1.y;
            #pragma unroll
            for (int j = 0; j < 24; j++) {
                const float2 aa = *(const float2*)(sAB + j * 36 + r0);
                const ulonglong2 gg = *(const ulonglong2*)(sG + j * 36 + k0);
                const ull a0 = pack2(aa.x), a1 = pack2(aa.y);
                ffma2(aL0, a0, gg.x); ffma2(aH0, a0, gg.y);
                ffma2(aL1, a1, gg.x); ffma2(aH1, a1, gg.y);
            }
            float2 r0lo = unpack2(aL0), r0hi = unpack2(aH0);
            float2 r1lo = unpack2(aL1), r1hi = unpack2(aH1);
            if (r0 >= 24) {
                float v0[4] = { r0lo.x, r0lo.y, r0hi.x, r0hi.y };
                float v1[4] = { r1lo.x, r1lo.y, r1hi.x, r1hi.y };
                const int d0 = r0 - k0;
                if (d0 >= 0 && d0 < 4) v0[d0] += REGU;
                const int d1 = r0 + 1 - k0;
                if (d1 >= 0 && d1 < 4) v1[d1] += REGU;
                *(float4*)(sH + r0 * 36 + k0)       = make_float4(v0[0], v0[1], v0[2], v0[3]);
                *(float4*)(sH + (r0 + 1) * 36 + k0) = make_float4(v1[0], v1[1], v1[2], v1[3]);
            } else {
                *(float4*)(sH + r0 * 36 + k0)       = make_float4(r0lo.x, r0lo.y, r0hi.x, r0hi.y);
                *(float4*)(sH + (r0 + 1) * 36 + k0) = make_float4(r1lo.x, r1lo.y, r1hi.x, r1hi.y);
            }
        }
        __syncthreads();

        // ---- stage C: warp0 augmented GJ on [Quu | Qux | Qu] -> K, kv
        //      warps 1-3: commit prefetched tile
        if (tid < 32) {
            const int seg = tid >> 3, r = tid & 7;
            float m[9];
            if (seg == 0) {
                #pragma unroll
                for (int j = 0; j < 8; j++)
                    m[j] = (j <= r) ? sH[(24 + r) * 36 + 24 + j]
                                    : sH[(24 + j) * 36 + 24 + r];
                m[8] = sQ[24 + r];
            } else {
                const int cb = (seg - 1) * 8;
                #pragma unroll
                for (int j = 0; j < 8; j++)
                    m[j] = sH[(24 + r) * 36 + cb + j];
                m[8] = 0.f;
            }
            #pragma unroll
            for (int cc = 0; cc < 8; cc++) {
                const float p   = __shfl_sync(0xffffffffu, m[cc], cc);
                const float inv = __fdividef(1.0f, p);
                const float f   = __shfl_sync(0xffffffffu, m[cc], r);
                const float fi  = f * inv;
                const int src = (seg << 3) | cc;
                float pr[9];
                #pragma unroll
                for (int j = 0; j < 9; j++) pr[j] = __shfl_sync(0xffffffffu, m[j], src);
                const bool isPiv = (r == cc);
                #pragma unroll
                for (int j = 0; j < 9; j++)
                    m[j] = isPiv ? (m[j] * inv) : (m[j] - fi * pr[j]);
            }
            if (seg == 0) {
                skv[r] = -m[8];
                g_kv[(size_t)(b * T_HOR + t) * 8 + r] = -m[8];
            } else {
                const int cb = (seg - 1) * 8;
                const float4 k0v = make_float4(-m[0], -m[1], -m[2], -m[3]);
                const float4 k1v = make_float4(-m[4], -m[5], -m[6], -m[7]);
                *(float4*)(sK + r * 28 + cb)     = k0v;
                *(float4*)(sK + r * 28 + cb + 4) = k1v;
                float* gk = g_K + (size_t)(b * T_HOR + t) * 192 + r * 24 + cb;
                *(float4*)gk       = k0v;
                *(float4*)(gk + 4) = k1v;
            }
        } else if (t > 0) {
            const int idx = tid - 32;
            *(float4*)(sC + (idx >> 3) * 36 + ((idx & 7) << 2)) = pc0;
            {
                const int s = idx + 96;
                *(float4*)(sC + (s >> 3) * 36 + ((s & 7) << 2)) = pc1;
            }
            if (tid < 96) {
                const int s = idx + 192;
                *(float4*)(sC + (s >> 3) * 36 + ((s & 7) << 2)) = pc2;
            }
            if (tid < 64) sc2[tid - 32] = psc;
            else if (tid < 88) szref[tid - 64] = psc;
            else if (tid < 96) szref[24 + tid - 88] = psc;
        }
        __syncthreads();

        // ---- stage E: V = H_tri + 0.5*S (42 thr, 2 rows each, f32x2) ; vn (24 thr)
        if (tid < 42) {
            const int i0 = 4 * e_ti, k0 = 4 * e_tk;
            const int rh = i0 + (tid & 1) * 2;
            ull sL0 = 0, sH0 = 0, sL1 = 0, sH1 = 0;
            #pragma unroll
            for (int a = 0; a < 8; a++) {
                const float2 hi = *(const float2*)(sH + (24 + a) * 36 + rh);
                const float2 ki = *(const float2*)(sK + a * 28 + rh);
                const ulonglong2 hk = *(const ulonglong2*)(sH + (24 + a) * 36 + k0);
                const ulonglong2 kk = *(const ulonglong2*)(sK + a * 28 + k0);
                const ull h0 = pack2(hi.x), k0p = pack2(ki.x);
                const ull h1 = pack2(hi.y), k1p = pack2(ki.y);
                ffma2(sL0, h0, kk.x); ffma2(sH0, h0, kk.y);
                ffma2(sL0, k0p, hk.x); ffma2(sH0, k0p, hk.y);
                ffma2(sL1, h1, kk.x); ffma2(sH1, h1, kk.y);
                ffma2(sL1, k1p, hk.x); ffma2(sH1, k1p, hk.y);
            }
            const float2 s0a = unpack2(sL0), s0b = unpack2(sH0);
            const float2 s1a = unpack2(sL1), s1b = unpack2(sH1);
            const float S0[4] = { s0a.x, s0a.y, s0b.x, s0b.y };
            const float S1[4] = { s1a.x, s1a.y, s1b.x, s1b.y };
            if (e_ti == e_tk) {
                float v0[4], v1[4];
                #pragma unroll
                for (int c = 0; c < 4; c++) {
                    const int gc = k0 + c;
                    const float h0 = (gc > rh)     ? sH[gc * 36 + rh]     : sH[rh * 36 + gc];
                    const float h1 = (gc > rh + 1) ? sH[gc * 36 + rh + 1] : sH[(rh + 1) * 36 + gc];
                    v0[c] = h0 + 0.5f * S0[c];
                    v1[c] = h1 + 0.5f * S1[c];
                }
                *(float4*)(sV + rh * 28 + k0)       = make_float4(v0[0], v0[1], v0[2], v0[3]);
                *(float4*)(sV + (rh + 1) * 28 + k0) = make_float4(v1[0], v1[1], v1[2], v1[3]);
            } else {
                float v0[4], v1[4];
                #pragma unroll
                for (int c = 0; c < 4; c++) {
                    v0[c] = sH[rh * 36 + k0 + c] + 0.5f * S0[c];
                    v1[c] = sH[(rh + 1) * 36 + k0 + c] + 0.5f * S1[c];
                    sV[(k0 + c) * 28 + rh]     = v0[c];   // mirror
                    sV[(k0 + c) * 28 + rh + 1] = v1[c];
                }
                *(float4*)(sV + rh * 28 + k0)       = make_float4(v0[0], v0[1], v0[2], v0[3]);
                *(float4*)(sV + (rh + 1) * 28 + k0) = make_float4(v1[0], v1[1], v1[2], v1[3]);
            }
        } else if (tid >= 96 && tid < 120) {
            const int i = tid - 96;
            float acc = sQ[i];
            #pragma unroll
            for (int a = 0; a < 8; a++) acc += sH[(24 + a) * 36 + i] * skv[a];
            sv[i] = acc;
        }
        __syncthreads();
    }

    // ---------------- forward rollout ----------------
    float* ob = d_out + (size_t)b * 3224;
    if (tid < 24) {
        const float xi = d_x0[b * 24 + tid];
        sx[0][tid] = xi;
        ob[tid] = xi;
    }
    float kr0 = 0.f, kr1 = 0.f;
    if (tid < 96) {
        const float2 k2 = *(const float2*)(g_K + (size_t)b * T_HOR * 192 + 2 * tid);
        kr0 = k2.x; kr1 = k2.y;
    } else if (tid < 104) {
        kr0 = g_kv[(size_t)b * T_HOR * 8 + (tid - 96)];
    }
    __syncthreads();

    int cur = 0;
    for (int t = 0; t < T_HOR; t++) {
        if (tid < 96)
            *(float2*)(sK2 + 2 * tid) = make_float2(kr0, kr1);
        else if (tid < 104)
            skv[tid - 96] = kr0;
        __syncthreads();
        if (t < T_HOR - 1) {
            if (tid < 96) {
                const float2 k2 = *(const float2*)(g_K + (size_t)(b * T_HOR + t + 1) * 192 + 2 * tid);
                kr0 = k2.x; kr1 = k2.y;
            } else if (tid < 104) {
                kr0 = g_kv[(size_t)(b * T_HOR + t + 1) * 8 + (tid - 96)];
            }
        }
        {
            const int a = tid >> 4, l = tid & 15;
            float p = 0.f;
            if (l < 12)
                p = sK2[a * 24 + l] * sx[cur][l] + sK2[a * 24 + l + 12] * sx[cur][l + 12];
            p += __shfl_down_sync(0xffffffffu, p, 8, 16);
            p += __shfl_down_sync(0xffffffffu, p, 4, 16);
            p += __shfl_down_sync(0xffffffffu, p, 2, 16);
            p += __shfl_down_sync(0xffffffffu, p, 1, 16);
            if (l == 0) {
                const float u = p + skv[a];
                su[a] = u;
                ob[2424 + t * 8 + a] = u;
            }
        }
        __syncthreads();
        if (tid < 24) {
            float acc = 0.f;
            #pragma unroll
            for (int j = 0; j < 24; j++) acc += sAB[tid * 36 + j] * sx[cur][j];
            #pragma unroll
            for (int a = 0; a < 8; a++) acc += sAB[tid * 36 + 24 + a] * su[a];
            sx[1 - cur][tid] = acc;
            ob[(t + 1) * 24 + tid] = acc;
        }
        __syncthreads();
        cur = 1 - cur;
    }
}

extern "C" void kernel_launch(void* const* d_in, const int* in_sizes, int n_in,
                              void* d_out, int out_size)
{
    const float* x0   = (const float*)d_in[0];
    const float* C    = (const float*)d_in[1];
    const float* c    = (const float*)d_in[2];
    const float* Cf   = (const float*)d_in[3];
    const float* cf   = (const float*)d_in[4];
    const float* xref = (const float*)d_in[5];
    const float* uref = (const float*)d_in[6];
    const float* A    = (const float*)d_in[7];
    const float* B    = (const float*)d_in[8];

    lqr_kernel<<<B_BATCH, 128>>>(x0, C, c, Cf, cf, xref, uref, A, B, (float*)d_out);
}